// round 13
// baseline (speedup 1.0000x reference)
#include <cuda_runtime.h>
#include <stdint.h>

#define B_SZ 16
#define T_SZ 8192
#define H_SZ 256
#define MTOT (B_SZ * T_SZ)   // 131072 rows

// fp16 copies (allocation-free scratch)
__device__ uint16_t g_xh[(size_t)MTOT * H_SZ];          // 64 MiB
__device__ uint16_t g_wh[2 * H_SZ * H_SZ];              // Wlin | Wmem, 256 KiB

#define NK 16                 // k16 chunks
#define NBUF 6
#define ASTRIDE 48            // bytes per smem row (32B data + 16B pad)
#define ABYTES (144 * ASTRIDE)            // 6912
#define BLOFF ABYTES
#define BMOFF (ABYTES + 32 * ASTRIDE)     // 8448
#define BUFB  (ABYTES + 64 * ASTRIDE)     // 9984 ; x6 = 59904
#define EPI_STRIDE 36
#define V_OFF  (128 * EPI_STRIDE * 4)             // 18432
#define DYN_SMEM (NBUF * BUFB)                    // 59904 (epi needs 38016)

__device__ __forceinline__ uint32_t smem_u32(const void* p) {
    uint32_t a;
    asm("{ .reg .u64 t; cvta.to.shared.u64 t, %1; cvt.u32.u64 %0, t; }" : "=r"(a) : "l"(p));
    return a;
}
__device__ __forceinline__ uint32_t pack_h2(float lo, float hi) {
    uint32_t r;
    asm("cvt.rn.f16x2.f32 %0, %1, %2;" : "=r"(r) : "f"(hi), "f"(lo));
    return r;
}
__device__ __forceinline__ void mma_f16(float* c, const uint32_t* a, const uint32_t* b) {
    asm volatile(
        "mma.sync.aligned.m16n8k16.row.col.f32.f16.f16.f32 "
        "{%0,%1,%2,%3}, {%4,%5,%6,%7}, {%8,%9}, {%0,%1,%2,%3};\n"
        : "+f"(c[0]), "+f"(c[1]), "+f"(c[2]), "+f"(c[3])
        : "r"(a[0]), "r"(a[1]), "r"(a[2]), "r"(a[3]), "r"(b[0]), "r"(b[1]));
}
#define LDSM_X4(r, addr) \
    asm volatile("ldmatrix.sync.aligned.m8n8.x4.shared.b16 {%0,%1,%2,%3}, [%4];" \
        : "=r"((r)[0]), "=r"((r)[1]), "=r"((r)[2]), "=r"((r)[3]) : "r"(addr))
#define CP_A16(dst, src, zf) \
    asm volatile("cp.async.ca.shared.global [%0], [%1], 16, %2;" \
        :: "r"(dst), "l"(src), "r"(zf) : "memory")
#define CP_COMMIT() asm volatile("cp.async.commit_group;" ::: "memory")
#define CP_WAIT(n)  asm volatile("cp.async.wait_group %0;" :: "n"(n) : "memory")
#define STS_V2(addr, x, y) \
    asm volatile("st.shared.v2.b32 [%0], {%1,%2};" :: "r"(addr), \
        "r"(__float_as_uint(x)), "r"(__float_as_uint(y)))

// ---------------- pre-pass: fp32 -> fp16 ----------------
__global__ __launch_bounds__(256) void cvt_x(const float* __restrict__ X) {
    const int idx = blockIdx.x * 256 + threadIdx.x;
    const float4 a = *(const float4*)(X + (size_t)idx * 8);
    const float4 b = *(const float4*)(X + (size_t)idx * 8 + 4);
    uint4 o;
    o.x = pack_h2(a.x, a.y); o.y = pack_h2(a.z, a.w);
    o.z = pack_h2(b.x, b.y); o.w = pack_h2(b.z, b.w);
    ((uint4*)g_xh)[idx] = o;
}
__global__ __launch_bounds__(256) void cvt_w(const float* __restrict__ Wlin,
                                             const float* __restrict__ Wmem) {
    const int idx = blockIdx.x * 256 + threadIdx.x;
    const float* src = (idx < 8192) ? (Wlin + (size_t)idx * 8)
                                    : (Wmem + (size_t)(idx - 8192) * 8);
    const float4 a = *(const float4*)src;
    const float4 b = *(const float4*)(src + 4);
    uint4 o;
    o.x = pack_h2(a.x, a.y); o.y = pack_h2(a.z, a.w);
    o.z = pack_h2(b.x, b.y); o.w = pack_h2(b.z, b.w);
    ((uint4*)g_wh)[idx] = o;
}

// ---------------- fused GEMM + window ----------------
// grid (8 col-eighths fastest, 1024 row-tiles), 256 threads, 3 CTAs/SM target.
// CTA: out[mbase..+127][nbase..+31], both weights. warps 0-3: u, 4-7: v (+halo).
// Each warp: 32 rows (mi=2) x 32 cols (ni=4) -> 32 acc regs. v-warp w also does
// one halo mma (16 halo rows x its 8-col block w).
__global__ __launch_bounds__(256, 3)
void fsmn_fused(const float* __restrict__ blin,
                const float* __restrict__ bmem,
                float* __restrict__ out)
{
    extern __shared__ char smem_raw[];
    const uint32_t sbase = smem_u32(smem_raw);

    const int tid  = threadIdx.x;
    const int wid  = tid >> 5;
    const int lane = tid & 31;
    const int rt    = blockIdx.y;
    const int mbase = rt * 128;
    const int nbase = blockIdx.x * 32;

    const bool isU = (wid < 4);
    const int  w   = wid & 3;
    const int  wm  = w * 32;            // 32 rows per warp
    const int  g   = lane >> 2;
    const int  cq  = lane & 3;

    const uint32_t aLane = (uint32_t)((lane & 7) + ((lane >> 3) & 1) * 8) * ASTRIDE
                         + ((lane >> 4) & 1) * 16;
    // B: all 32 n-rows per warp (two LDSM_X4: rows 0-15, 16-31)
    const uint32_t bLane = (uint32_t)((lane & 7) + ((lane >> 4) & 1) * 8) * ASTRIDE
                         + ((lane >> 3) & 1) * 16;

    // ---- staging: 416 cp.async granules (16B = 8 halfs) per k-chunk ----
    const bool firstB = ((rt & 63) == 0);
    uint32_t st_dst[2]; const uint16_t* st_src[2]; uint32_t st_zf[2]; int st_on[2];
    #pragma unroll
    for (int q = 0; q < 2; ++q) {
        const int idx = tid + q * 256;
        st_on[q] = (idx < 416); st_zf[q] = 16; st_dst[q] = 0; st_src[q] = g_xh;
        if (idx < 288) {                       // A: 144 rows x 2 granules
            const int sub = (idx >= 144);
            const int row = idx - sub * 144;
            st_dst[q] = (uint32_t)row * ASTRIDE + (uint32_t)sub * 16;
            const int z = (firstB && row < 16);
            st_src[q] = z ? g_xh : (g_xh + (size_t)(mbase - 16 + row) * H_SZ + sub * 8);
            st_zf[q]  = z ? 0u : 16u;
        } else if (idx < 416) {                // Wlin 32x2 then Wmem 32x2
            const int j   = idx - 288;         // 0..127
            const int mat = (j >= 64);
            const int jj  = j - mat * 64;
            const int sub = (jj >= 32);
            const int row = jj - sub * 32;
            st_dst[q] = (mat ? BMOFF : BLOFF) + (uint32_t)row * ASTRIDE + (uint32_t)sub * 16;
            st_src[q] = g_wh + (size_t)mat * H_SZ * H_SZ + (size_t)(nbase + row) * H_SZ + sub * 8;
        }
    }

#define STAGE(ktv) do {                                                        \
        const uint32_t _db = sbase + (uint32_t)((ktv) % NBUF) * BUFB;          \
        const int _ko = (ktv) * 16;                                            \
        _Pragma("unroll")                                                      \
        for (int q = 0; q < 2; ++q)                                            \
            if (st_on[q])                                                      \
                CP_A16(_db + st_dst[q], st_src[q] + _ko, st_zf[q]);            \
        CP_COMMIT();                                                           \
    } while (0)

    float acc[2][4][4];
    #pragma unroll
    for (int i = 0; i < 2; i++)
        #pragma unroll
        for (int j = 0; j < 4; j++)
            #pragma unroll
            for (int k = 0; k < 4; k++) acc[i][j][k] = 0.f;
    float acch[4] = {0.f, 0.f, 0.f, 0.f};

    const uint32_t bSel = isU ? (uint32_t)BLOFF : (uint32_t)BMOFF;

#define PROCESS(ktv) do {                                                      \
        const uint32_t Abuf = sbase + (uint32_t)((ktv) % NBUF) * BUFB;         \
        const uint32_t Bbuf = Abuf + bSel;                                     \
        uint32_t bf[8];                                                        \
        LDSM_X4(bf,     Bbuf + bLane);                  /* n-blocks 0, 8   */  \
        LDSM_X4(bf + 4, Bbuf + bLane + 16 * ASTRIDE);   /* n-blocks 16, 24 */  \
        _Pragma("unroll")                                                      \
        for (int mi = 0; mi < 2; ++mi) {                                       \
            uint32_t af[4];                                                    \
            LDSM_X4(af, Abuf + aLane + (uint32_t)(16 + wm + mi * 16) * ASTRIDE); \
            mma_f16(acc[mi][0], af, bf + 0);                                   \
            mma_f16(acc[mi][1], af, bf + 2);                                   \
            mma_f16(acc[mi][2], af, bf + 4);                                   \
            mma_f16(acc[mi][3], af, bf + 6);                                   \
        }                                                                      \
        if (!isU) {                        /* 16 halo rows x 8-col block w */  \
            uint32_t ah[4];                                                    \
            LDSM_X4(ah, Abuf + aLane);                                         \
            mma_f16(acch, ah, bf + 2 * w);                                     \
        }                                                                      \
    } while (0)

    STAGE(0); STAGE(1); STAGE(2); STAGE(3);

    for (int kt = 0; kt < NK; kt += 2) {
        if (kt + 2 < NK) { CP_WAIT(2); } else { CP_WAIT(0); }
        __syncthreads();
        if (kt + 4 < NK) STAGE(kt + 4);
        if (kt + 5 < NK) STAGE(kt + 5);
        PROCESS(kt);
        PROCESS(kt + 1);
    }

    // ================= epilogue =================
    __syncthreads();
    {
        const uint32_t sb = sbase + (isU ? 0u : (uint32_t)V_OFF + 8u * EPI_STRIDE * 4);
        #pragma unroll
        for (int mi = 0; mi < 2; ++mi) {
            const int r = wm + mi * 16 + g;
            #pragma unroll
            for (int ni = 0; ni < 4; ++ni) {
                const int col = ni * 8 + cq * 2;
                STS_V2(sb + (uint32_t)(r * EPI_STRIDE + col) * 4,
                       acc[mi][ni][0], acc[mi][ni][1]);
                STS_V2(sb + (uint32_t)((r + 8) * EPI_STRIDE + col) * 4,
                       acc[mi][ni][2], acc[mi][ni][3]);
            }
        }
        if (!isU) {   // halo: keep lower 8 rows (out rows mbase-8..-1) -> V rows g
            const int col = w * 8 + cq * 2;
            STS_V2(sbase + (uint32_t)V_OFF + (uint32_t)(g * EPI_STRIDE + col) * 4,
                   acch[2], acch[3]);
        }
    }
    __syncthreads();

    // window + combine + store. thread: col c (0..31), 16-row segment seg (0..7).
    {
        const int c   = tid & 31;
        const int seg = tid >> 5;
        const float bias = __ldg(&blin[nbase + c]) + __ldg(&bmem[nbase + c]);
        const float* U = (const float*)smem_raw;
        const float* V = (const float*)(smem_raw + V_OFF);

        float sum = 0.f;
        #pragma unroll
        for (int j = 0; j < 8; ++j)
            sum += V[(seg * 16 + j) * EPI_STRIDE + c];

        const int tloc0 = (rt & 63) * 128 + seg * 16;
        #pragma unroll 4
        for (int i = 0; i < 16; ++i) {
            const int R = seg * 16 + i;
            sum += V[(R + 8) * EPI_STRIDE + c];
            const int t = tloc0 + i;
            const float inv = (t >= 8) ? (1.0f / 9.0f) : (1.0f / (float)(t + 1));
            out[(size_t)(mbase + R) * H_SZ + nbase + c] =
                U[R * EPI_STRIDE + c] + sum * inv + bias;
            sum -= V[R * EPI_STRIDE + c];
        }
    }
#undef STAGE
#undef PROCESS
}

extern "C" void kernel_launch(void* const* d_in, const int* in_sizes, int n_in,
                              void* d_out, int out_size)
{
    const float* x    = (const float*)d_in[0];
    const float* Wlin = (const float*)d_in[1];
    const float* blin = (const float*)d_in[2];
    const float* Wmem = (const float*)d_in[3];
    const float* bmem = (const float*)d_in[4];
    float* out = (float*)d_out;

    cudaFuncSetAttribute(fsmn_fused, cudaFuncAttributeMaxDynamicSharedMemorySize, DYN_SMEM);
    cvt_x<<<(MTOT * H_SZ / 8) / 256, 256>>>(x);
    cvt_w<<<(2 * H_SZ * H_SZ / 8) / 256, 256>>>(Wlin, Wmem);
    dim3 grid(8, MTOT / 128, 1);
    fsmn_fused<<<grid, 256, DYN_SMEM>>>(blin, bmem, out);
}

// round 15
// speedup vs baseline: 1.4003x; 1.4003x over previous
#include <cuda_runtime.h>
#include <stdint.h>

#define B_SZ 16
#define T_SZ 8192
#define H_SZ 256
#define MTOT (B_SZ * T_SZ)   // 131072 rows

// fp16 copies (allocation-free scratch)
__device__ uint16_t g_xh[(size_t)MTOT * H_SZ];          // 64 MiB
__device__ uint16_t g_wh[2 * H_SZ * H_SZ];              // Wlin | Wmem, 256 KiB

#define NK 16                 // k16 chunks
#define NBUF 6
// Contiguous-matrix layout: tile row r, 16B-half h -> (r>>3)*256 + h*128 + (r&7)*16.
// Every 8x8 b16 ldmatrix tile is ONE contiguous 128-B line.
#define ABYTES (144 * 32)                 // 4608
#define BLOFF ABYTES                      // 4608
#define BMOFF (ABYTES + 64 * 32)          // 6656
#define BUFB  (ABYTES + 128 * 32)         // 8704 ; x6 = 52224
#define EPI_STRIDE 68
#define V_OFF  (128 * EPI_STRIDE * 4)             // 34816
#define EPI_BYTES (V_OFF + 136 * EPI_STRIDE * 4)  // 71808
#define DYN_SMEM EPI_BYTES                        // 71808 (>= 6*BUFB)

__device__ __forceinline__ uint32_t smem_u32(const void* p) {
    uint32_t a;
    asm("{ .reg .u64 t; cvta.to.shared.u64 t, %1; cvt.u32.u64 %0, t; }" : "=r"(a) : "l"(p));
    return a;
}
__device__ __forceinline__ uint32_t pack_h2(float lo, float hi) {
    uint32_t r;
    asm("cvt.rn.f16x2.f32 %0, %1, %2;" : "=r"(r) : "f"(hi), "f"(lo));
    return r;
}
__device__ __forceinline__ void mma_f16(float* c, const uint32_t* a, const uint32_t* b) {
    asm volatile(
        "mma.sync.aligned.m16n8k16.row.col.f32.f16.f16.f32 "
        "{%0,%1,%2,%3}, {%4,%5,%6,%7}, {%8,%9}, {%0,%1,%2,%3};\n"
        : "+f"(c[0]), "+f"(c[1]), "+f"(c[2]), "+f"(c[3])
        : "r"(a[0]), "r"(a[1]), "r"(a[2]), "r"(a[3]), "r"(b[0]), "r"(b[1]));
}
#define LDSM_X4(r, addr) \
    asm volatile("ldmatrix.sync.aligned.m8n8.x4.shared.b16 {%0,%1,%2,%3}, [%4];" \
        : "=r"((r)[0]), "=r"((r)[1]), "=r"((r)[2]), "=r"((r)[3]) : "r"(addr))
#define CP_A16(dst, src, zf) \
    asm volatile("cp.async.ca.shared.global [%0], [%1], 16, %2;" \
        :: "r"(dst), "l"(src), "r"(zf) : "memory")
#define CP_COMMIT() asm volatile("cp.async.commit_group;" ::: "memory")
#define CP_WAIT(n)  asm volatile("cp.async.wait_group %0;" :: "n"(n) : "memory")
#define STS_V2(addr, x, y) \
    asm volatile("st.shared.v2.b32 [%0], {%1,%2};" :: "r"(addr), \
        "r"(__float_as_uint(x)), "r"(__float_as_uint(y)))

// ---------------- pre-pass: fp32 -> fp16 ----------------
__global__ __launch_bounds__(256) void cvt_x(const float* __restrict__ X) {
    const int idx = blockIdx.x * 256 + threadIdx.x;
    const float4 a = *(const float4*)(X + (size_t)idx * 8);
    const float4 b = *(const float4*)(X + (size_t)idx * 8 + 4);
    uint4 o;
    o.x = pack_h2(a.x, a.y); o.y = pack_h2(a.z, a.w);
    o.z = pack_h2(b.x, b.y); o.w = pack_h2(b.z, b.w);
    ((uint4*)g_xh)[idx] = o;
}
__global__ __launch_bounds__(256) void cvt_w(const float* __restrict__ Wlin,
                                             const float* __restrict__ Wmem) {
    const int idx = blockIdx.x * 256 + threadIdx.x;
    const float* src = (idx < 8192) ? (Wlin + (size_t)idx * 8)
                                    : (Wmem + (size_t)(idx - 8192) * 8);
    const float4 a = *(const float4*)src;
    const float4 b = *(const float4*)(src + 4);
    uint4 o;
    o.x = pack_h2(a.x, a.y); o.y = pack_h2(a.z, a.w);
    o.z = pack_h2(b.x, b.y); o.w = pack_h2(b.z, b.w);
    ((uint4*)g_wh)[idx] = o;
}

// ---------------- fused GEMM + window ----------------
// grid (4 col-quarters fastest, 1024 row-tiles), 256 threads, 2 CTAs/SM.
// CTA: out[mbase..+127][nbase..+63], both weights. warps 0-3: u, 4-7: v (+16-row halo).
// 6-buffer cp.async ring, one barrier per two k-steps, contiguous-matrix layout.
__global__ __launch_bounds__(256, 2)
void fsmn_fused(const float* __restrict__ blin,
                const float* __restrict__ bmem,
                float* __restrict__ out)
{
    extern __shared__ char smem_raw[];
    const uint32_t sbase = smem_u32(smem_raw);

    const int tid  = threadIdx.x;
    const int wid  = tid >> 5;
    const int lane = tid & 31;
    const int rt    = blockIdx.y;
    const int mbase = rt * 128;
    const int nbase = blockIdx.x * 64;

    const bool isU = (wid < 4);
    const int  w   = wid & 3;
    const int  wm  = (w >> 1) * 64;
    const int  wn  = (w & 1) * 32;
    const int  g   = lane >> 2;
    const int  cq  = lane & 3;

    // contiguous-matrix lane offsets:
    // A matrix i = lane>>3: (i&1)->rowblock(+8 rows => +256), (i>>1)->k-half(+128)
    const uint32_t aLane = ((lane >> 3) & 1) * 256 + ((lane >> 4) & 1) * 128
                         + (lane & 7) * 16;
    // B matrix i: (i>>1)->n-block(+8 rows => +256), (i&1)->k-half(+128); +wn rows
    const uint32_t bLane = (uint32_t)wn * 32 + ((lane >> 4) & 1) * 256
                         + ((lane >> 3) & 1) * 128 + (lane & 7) * 16;

    // ---- staging: 544 cp.async granules (16B = 8 halfs) per k-chunk ----
    const bool firstB = ((rt & 63) == 0);
    uint32_t st_dst[3]; const uint16_t* st_src[3]; uint32_t st_zf[3]; int st_on[3];
    #pragma unroll
    for (int q = 0; q < 3; ++q) {
        const int idx = tid + q * 256;
        st_on[q] = (idx < 544); st_zf[q] = 16; st_dst[q] = 0; st_src[q] = g_xh;
        if (idx < 288) {                       // A: 144 rows x 2 halves
            const int sub = (idx >= 144);
            const int row = idx - sub * 144;
            st_dst[q] = (uint32_t)(row >> 3) * 256 + (uint32_t)sub * 128
                      + (uint32_t)(row & 7) * 16;
            const int z = (firstB && row < 16);
            st_src[q] = z ? g_xh : (g_xh + (size_t)(mbase - 16 + row) * H_SZ + sub * 8);
            st_zf[q]  = z ? 0u : 16u;
        } else if (idx < 544) {                // Wlin then Wmem: 64 rows x 2 each
            const int j   = idx - 288;
            const int mat = (j >= 128);
            const int jj  = j - mat * 128;
            const int sub = (jj >= 64);
            const int row = jj - sub * 64;
            st_dst[q] = (mat ? BMOFF : BLOFF) + (uint32_t)(row >> 3) * 256
                      + (uint32_t)sub * 128 + (uint32_t)(row & 7) * 16;
            st_src[q] = g_wh + (size_t)mat * H_SZ * H_SZ + (size_t)(nbase + row) * H_SZ + sub * 8;
        }
    }

#define STAGE(ktv) do {                                                        \
        const uint32_t _db = sbase + (uint32_t)((ktv) % NBUF) * BUFB;          \
        const int _ko = (ktv) * 16;                                            \
        _Pragma("unroll")                                                      \
        for (int q = 0; q < 3; ++q)                                            \
            if (st_on[q])                                                      \
                CP_A16(_db + st_dst[q], st_src[q] + _ko, st_zf[q]);            \
        CP_COMMIT();                                                           \
    } while (0)

    float acc[4][4][4];
    #pragma unroll
    for (int i = 0; i < 4; i++)
        #pragma unroll
        for (int j = 0; j < 4; j++)
            #pragma unroll
            for (int k = 0; k < 4; k++) acc[i][j][k] = 0.f;
    float acch[2][4];
    #pragma unroll
    for (int i = 0; i < 2; i++)
        #pragma unroll
        for (int k = 0; k < 4; k++) acch[i][k] = 0.f;

    const uint32_t bSel = isU ? (uint32_t)BLOFF : (uint32_t)BMOFF;
    const int haloBase = (w >> 1) * 4;

#define PROCESS(ktv) do {                                                      \
        const uint32_t Abuf = sbase + (uint32_t)((ktv) % NBUF) * BUFB;         \
        const uint32_t Bbuf = Abuf + bSel;                                     \
        uint32_t bf[8];                                                        \
        LDSM_X4(bf,     Bbuf + bLane);           /* n-blocks wn, wn+8   */     \
        LDSM_X4(bf + 4, Bbuf + bLane + 512);     /* n-blocks wn+16, +24 */     \
        _Pragma("unroll")                                                      \
        for (int mi = 0; mi < 4; ++mi) {                                       \
            uint32_t af[4];                                                    \
            LDSM_X4(af, Abuf + aLane + (uint32_t)(16 + wm + mi * 16) * 32);    \
            mma_f16(acc[mi][0], af, bf + 0);                                   \
            mma_f16(acc[mi][1], af, bf + 2);                                   \
            mma_f16(acc[mi][2], af, bf + 4);                                   \
            mma_f16(acc[mi][3], af, bf + 6);                                   \
        }                                                                      \
        if (!isU) {                            /* halo: A rows 0..15 */        \
            uint32_t ah[4];                                                    \
            LDSM_X4(ah, Abuf + aLane);                                         \
            mma_f16(acch[0], ah, bf + haloBase + 0);                           \
            mma_f16(acch[1], ah, bf + haloBase + 2);                           \
        }                                                                      \
    } while (0)

    STAGE(0); STAGE(1); STAGE(2); STAGE(3);

    for (int kt = 0; kt < NK; kt += 2) {
        if (kt + 2 < NK) { CP_WAIT(2); } else { CP_WAIT(0); }
        __syncthreads();
        if (kt + 4 < NK) STAGE(kt + 4);
        if (kt + 5 < NK) STAGE(kt + 5);
        PROCESS(kt);
        PROCESS(kt + 1);
    }

    // ================= epilogue (identical to R11 passing layout) =================
    __syncthreads();
    {
        const uint32_t sb = sbase + (isU ? 0u : (uint32_t)V_OFF + 8u * EPI_STRIDE * 4);
        #pragma unroll
        for (int mi = 0; mi < 4; ++mi) {
            const int r = wm + mi * 16 + g;
            #pragma unroll
            for (int ni = 0; ni < 4; ++ni) {
                const int col = wn + ni * 8 + cq * 2;
                STS_V2(sb + (uint32_t)(r * EPI_STRIDE + col) * 4,
                       acc[mi][ni][0], acc[mi][ni][1]);
                STS_V2(sb + (uint32_t)((r + 8) * EPI_STRIDE + col) * 4,
                       acc[mi][ni][2], acc[mi][ni][3]);
            }
        }
        if (!isU) {   // halo: keep lower 8 rows (out rows mbase-8..-1) -> V rows g
            const int hb = (w & 1) * 32 + (w >> 1) * 16;
            #pragma unroll
            for (int nil = 0; nil < 2; ++nil) {
                const int col = hb + nil * 8 + cq * 2;
                STS_V2(sbase + (uint32_t)V_OFF + (uint32_t)(g * EPI_STRIDE + col) * 4,
                       acch[nil][2], acch[nil][3]);
            }
        }
    }
    __syncthreads();

    // window + combine + store
    {
        const int c   = tid & 63;
        const int seg = tid >> 6;
        const float bias = __ldg(&blin[nbase + c]) + __ldg(&bmem[nbase + c]);
        const float* U = (const float*)smem_raw;
        const float* V = (const float*)(smem_raw + V_OFF);

        float sum = 0.f;
        #pragma unroll
        for (int j = 0; j < 8; ++j)
            sum += V[(seg * 32 + j) * EPI_STRIDE + c];

        const int tloc0 = (rt & 63) * 128 + seg * 32;
        #pragma unroll 4
        for (int i = 0; i < 32; ++i) {
            const int R = seg * 32 + i;
            sum += V[(R + 8) * EPI_STRIDE + c];
            const int t = tloc0 + i;
            const float inv = (t >= 8) ? (1.0f / 9.0f) : (1.0f / (float)(t + 1));
            out[(size_t)(mbase + R) * H_SZ + nbase + c] =
                U[R * EPI_STRIDE + c] + sum * inv + bias;
            sum -= V[R * EPI_STRIDE + c];
        }
    }
#undef STAGE
#undef PROCESS
}

extern "C" void kernel_launch(void* const* d_in, const int* in_sizes, int n_in,
                              void* d_out, int out_size)
{
    const float* x    = (const float*)d_in[0];
    const float* Wlin = (const float*)d_in[1];
    const float* blin = (const float*)d_in[2];
    const float* Wmem = (const float*)d_in[3];
    const float* bmem = (const float*)d_in[4];
    float* out = (float*)d_out;

    cudaFuncSetAttribute(fsmn_fused, cudaFuncAttributeMaxDynamicSharedMemorySize, DYN_SMEM);
    cvt_x<<<(MTOT * H_SZ / 8) / 256, 256>>>(x);
    cvt_w<<<(2 * H_SZ * H_SZ / 8) / 256, 256>>>(Wlin, Wmem);
    dim3 grid(4, MTOT / 128, 1);
    fsmn_fused<<<grid, 256, DYN_SMEM>>>(blin, bmem, out);
}